// round 10
// baseline (speedup 1.0000x reference)
#include <cuda_runtime.h>
#include <cuda_bf16.h>
#include <math.h>
#include <stdint.h>

#define TOKENS 4096
#define DDIM   1024

// ---------------------------------------------------------------------------
// scratch (__device__ globals; no cudaMalloc allowed)
// x hi/lo bf16: 512 tiles of 128x64 (16KB, SW128-pre-swizzled)
// W1 hi/lo bf16: 64 tiles of 256x64 (32KB, SW128-pre-swizzled)
// ---------------------------------------------------------------------------
__device__ float g_s[TOKENS];
__device__ __align__(1024) uint4 g_xhi[512 * 1024];
__device__ __align__(1024) uint4 g_xlo[512 * 1024];
__device__ __align__(1024) uint4 g_whi[64 * 2048];
__device__ __align__(1024) uint4 g_wlo[64 * 2048];

__device__ __forceinline__ float softplusf(float z) {
    if (z > 20.0f) return z;
    return log1pf(expf(z));
}

__device__ __forceinline__ uint32_t smem_u32(const void* p) {
    uint32_t a;
    asm("{ .reg .u64 t; cvta.to.shared.u64 t, %1; cvt.u32.u64 %0, t; }"
        : "=r"(a) : "l"(p));
    return a;
}

#define MBARRIER_INIT(addr, cnt) \
    asm volatile("mbarrier.init.shared.b64 [%0], %1;" :: "r"(addr), "r"(cnt) : "memory")
#define MBARRIER_EXPECT_TX(addr, bytes) \
    asm volatile("mbarrier.arrive.expect_tx.shared.b64 _, [%0], %1;" \
        :: "r"(addr), "r"(bytes) : "memory")
#define MBARRIER_ARRIVE(addr) \
    asm volatile("mbarrier.arrive.shared.b64 _, [%0];" :: "r"(addr) : "memory")

#define MBARRIER_WAIT_PARITY(addr, parity) do { \
    uint32_t _m = (addr); uint32_t _p = (parity); uint32_t _d; \
    asm volatile("{\n\t.reg .pred p;\n\t" \
        "mbarrier.try_wait.parity.acquire.cta.shared::cta.b64 p, [%1], %2;\n\t" \
        "selp.b32 %0, 1, 0, p;\n\t}" : "=r"(_d) : "r"(_m), "r"(_p) : "memory"); \
    if (!_d) { \
        asm volatile("{\n\t.reg .pred P1;\n\t" \
            "WL_%=:\n\t" \
            "mbarrier.try_wait.parity.acquire.cta.shared::cta.b64 P1, [%0], %1, 0x989680;\n\t" \
            "@P1 bra.uni WD_%=;\n\t" \
            "bra.uni WL_%=;\n\t" \
            "WD_%=:\n\t}" :: "r"(_m), "r"(_p) : "memory"); \
    } \
} while (0)

__device__ __forceinline__ void bulk_g2s(uint32_t dst, const void* src,
                                         uint32_t bytes, uint32_t mbar) {
    asm volatile(
        "cp.async.bulk.shared::cluster.global.mbarrier::complete_tx::bytes "
        "[%0], [%1], %2, [%3];"
        :: "r"(dst), "l"(src), "r"(bytes), "r"(mbar) : "memory");
}

__device__ __forceinline__ void cp16(uint32_t dst, const void* src) {
    asm volatile("cp.async.cg.shared.global [%0], [%1], 16;"
                 :: "r"(dst), "l"(src) : "memory");
}
#define CP_COMMIT() asm volatile("cp.async.commit_group;" ::: "memory")
#define CP_WAIT1()  asm volatile("cp.async.wait_group 1;" ::: "memory")
#define CP_WAIT0()  asm volatile("cp.async.wait_group 0;" ::: "memory")

__device__ __forceinline__ void ldsm_x4(uint32_t* r, uint32_t addr) {
    asm volatile("ldmatrix.sync.aligned.m8n8.x4.shared.b16 {%0,%1,%2,%3}, [%4];"
                 : "=r"(r[0]), "=r"(r[1]), "=r"(r[2]), "=r"(r[3]) : "r"(addr));
}
__device__ __forceinline__ void mma16816(float* d, const uint32_t* a,
                                         const uint32_t* b) {
    asm volatile(
        "mma.sync.aligned.m16n8k16.row.col.f32.bf16.bf16.f32 "
        "{%0,%1,%2,%3}, {%4,%5,%6,%7}, {%8,%9}, {%0,%1,%2,%3};"
        : "+f"(d[0]), "+f"(d[1]), "+f"(d[2]), "+f"(d[3])
        : "r"(a[0]), "r"(a[1]), "r"(a[2]), "r"(a[3]), "r"(b[0]), "r"(b[1]));
}

// ---------------------------------------------------------------------------
// Kernel 0 (merged prep):
//  blocks 0..127   : s[t] via 2-stage cp.async pipeline (32 tokens/block)
//  blocks 128..639 : split x into bf16 hi/lo 128x64 tiles (SW128-pre-swizzled)
//  blocks 640..767 : split W1 into bf16 hi/lo 256x64 tiles (half-tile/block)
// ---------------------------------------------------------------------------
__global__ __launch_bounds__(256) void prep_kernel(
    const float* __restrict__ X, const float* __restrict__ W,
    const float* __restrict__ W2, const float* __restrict__ b2,
    const float* __restrict__ W3, const float* __restrict__ b3)
{
    __shared__ float sx[2][32][68];
    __shared__ float sw[2][32][68];
    __shared__ float sout[32][33];

    const int bid = blockIdx.x;
    const int tid = threadIdx.x;

    if (bid >= 128) {
        // ------------- convert part -------------
        const int cb = bid - 128;
        const float* src;
        uint4 *dhi, *dlo;
        int row_base;
        if (cb < 512) {
            int mb = cb >> 4, kb = cb & 15;
            src = X + (size_t)mb * 128 * DDIM + kb * 64;
            dhi = g_xhi + (size_t)cb * 1024;
            dlo = g_xlo + (size_t)cb * 1024;
            row_base = 0;
        } else {
            int t2 = cb - 512;                 // 0..127
            int t = t2 >> 1, half = t2 & 1;    // tile 0..63, half-tile
            int nb = t >> 4, kb = t & 15;
            src = W + (size_t)(nb * 256 + half * 128) * DDIM + kb * 64;
            dhi = g_whi + (size_t)t * 2048;
            dlo = g_wlo + (size_t)t * 2048;
            row_base = half * 128;
        }
        #pragma unroll
        for (int it = 0; it < 4; ++it) {
            int c = tid + it * 256;
            int row = c >> 3, c8 = c & 7;
            const float* p = src + (size_t)row * DDIM + c8 * 8;
            float4 v0 = *reinterpret_cast<const float4*>(p);
            float4 v1 = *reinterpret_cast<const float4*>(p + 4);
            float v[8] = {v0.x, v0.y, v0.z, v0.w, v1.x, v1.y, v1.z, v1.w};
            uint32_t ph[4], pl[4];
            #pragma unroll
            for (int i = 0; i < 4; ++i) {
                __nv_bfloat16 h0 = __float2bfloat16_rn(v[2 * i]);
                __nv_bfloat16 h1 = __float2bfloat16_rn(v[2 * i + 1]);
                __nv_bfloat16 l0 = __float2bfloat16_rn(v[2 * i]     - __bfloat162float(h0));
                __nv_bfloat16 l1 = __float2bfloat16_rn(v[2 * i + 1] - __bfloat162float(h1));
                ph[i] = (uint32_t)__bfloat16_as_ushort(h0) |
                        ((uint32_t)__bfloat16_as_ushort(h1) << 16);
                pl[i] = (uint32_t)__bfloat16_as_ushort(l0) |
                        ((uint32_t)__bfloat16_as_ushort(l1) << 16);
            }
            uint32_t off = (uint32_t)((row_base + row) * 128 + c8 * 16);
            off ^= ((off >> 3) & 0x70);   // SW128 swizzle, pre-applied
            dhi[off >> 4] = make_uint4(ph[0], ph[1], ph[2], ph[3]);
            dlo[off >> 4] = make_uint4(pl[0], pl[1], pl[2], pl[3]);
        }
        return;
    }

    // ------------- s part (bids 0..127): 2-stage cp.async pipeline ---------
    const int t0  = bid * 32;
    const int tok = tid & 31;
    const int g   = tid >> 5;

    const int ltk = tid >> 3;            // 0..31 (row for both x and w loads)
    const int lc4 = (tid & 7) * 2;       // f4-chunk base (2 chunks/thread)
    const float* wsrc = (ltk < 16) ? &W2[(size_t)ltk * DDIM]
                                   : &W3[(size_t)(ltk - 16) * DDIM];
    const float* xsrc = &X[(size_t)(t0 + ltk) * DDIM];

    #define S_LOAD(st, kt) do {                                            \
        int _k0 = (kt) * 64;                                               \
        _Pragma("unroll")                                                   \
        for (int _q = 0; _q < 2; ++_q) {                                    \
            int _c4 = lc4 + _q;                                             \
            cp16(smem_u32(&sx[st][ltk][_c4 * 4]), xsrc + _k0 + _c4 * 4);    \
            cp16(smem_u32(&sw[st][ltk][_c4 * 4]), wsrc + _k0 + _c4 * 4);    \
        }                                                                   \
        CP_COMMIT();                                                        \
    } while (0)

    float acc[4] = {0.f, 0.f, 0.f, 0.f};

    S_LOAD(0, 0);
    S_LOAD(1, 1);

    for (int kt = 0; kt < 16; ++kt) {
        const int st = kt & 1;
        if (kt == 15) { CP_WAIT0(); } else { CP_WAIT1(); }
        __syncthreads();
        #pragma unroll
        for (int k4 = 0; k4 < 16; ++k4) {
            float4 xv = *reinterpret_cast<const float4*>(&sx[st][tok][k4 * 4]);
            #pragma unroll
            for (int j = 0; j < 4; ++j) {
                float4 wv = *reinterpret_cast<const float4*>(&sw[st][g * 4 + j][k4 * 4]);
                acc[j] += xv.x * wv.x + xv.y * wv.y + xv.z * wv.z + xv.w * wv.w;
            }
        }
        __syncthreads();
        if (kt + 2 < 16) S_LOAD(st, kt + 2);
    }

    #pragma unroll
    for (int j = 0; j < 4; ++j) sout[tok][g * 4 + j] = acc[j];
    __syncthreads();

    if (tid < 32) {
        float s = 0.f;
        #pragma unroll
        for (int n = 0; n < 16; ++n)
            s += (sout[tid][n] + b2[n]) * (sout[tid][16 + n] + b3[n]);
        g_s[t0 + tid] = s;
    }
}

// ---------------------------------------------------------------------------
// Kernel 1: mma.sync bf16x3 GEMM, cp.async.bulk-fed, fused epilogue.
//   D = xhi@whi^T + xhi@wlo^T + xlo@whi^T; y = x * softplus(D + b1) * s
// BM=128, BN=256, BK=64, 2-stage bulk pipeline (96KB/stage), 544 threads:
//   warps 0-15 compute (32x64 tiles), warp 16 = producer.
// Grid = 4 x 32 = 128 CTAs -> exactly ONE wave on 148 SMs.
// B hi/lo share one register buffer to stay under the 120-reg ceiling.
// ---------------------------------------------------------------------------
#define NKT 16                    // 1024 / 64
#define STAGES 2
#define A_PART 16384              // 128x64 bf16
#define B_PART 32768              // 256x64 bf16
#define STAGE_B (2 * A_PART + 2 * B_PART)   // 98304
#define GEMM_SMEM (STAGES * STAGE_B)        // 196608

__global__ __launch_bounds__(544, 1) void gemm_kernel(
    const float* __restrict__ x,
    const float* __restrict__ b1,
    float* __restrict__ y)
{
    extern __shared__ __align__(1024) char smem[];
    __shared__ __align__(8) uint64_t mbar[2 * STAGES];  // full[0..1], empty[0..1]

    const uint32_t sdyn = smem_u32(smem);
    const uint32_t sFull  = smem_u32(&mbar[0]);
    const uint32_t sEmpty = smem_u32(&mbar[STAGES]);

    const int tid  = threadIdx.x;
    const int wid  = tid >> 5;
    const int lane = tid & 31;
    const int nb = blockIdx.x;          // 0..3
    const int mb = blockIdx.y;          // 0..31
    const int rbase = mb * 128;
    const int cbase = nb * 256;

    if (tid == 0) {
        #pragma unroll
        for (int s = 0; s < STAGES; ++s) {
            MBARRIER_INIT(sFull  + s * 8, 1);
            MBARRIER_INIT(sEmpty + s * 8, 16);
        }
    }
    __syncthreads();

    if (wid == 16) {
        // ---------------- producer ----------------
        if (lane == 0) {
            const char* xhiB = (const char*)g_xhi;
            const char* xloB = (const char*)g_xlo;
            const char* whiB = (const char*)g_whi;
            const char* wloB = (const char*)g_wlo;
            int st = 0, ph = 1;
            for (int kt = 0; kt < NKT; ++kt) {
                MBARRIER_WAIT_PARITY(sEmpty + st * 8, ph);
                uint32_t fb = sFull + st * 8;
                MBARRIER_EXPECT_TX(fb, STAGE_B);
                uint32_t sb = sdyn + st * STAGE_B;
                size_t ax = ((size_t)(mb * NKT + kt)) * A_PART;
                size_t bw = ((size_t)(nb * NKT + kt)) * B_PART;
                bulk_g2s(sb,                       xhiB + ax, A_PART, fb);
                bulk_g2s(sb + A_PART,              xloB + ax, A_PART, fb);
                bulk_g2s(sb + 2 * A_PART,          whiB + bw, B_PART, fb);
                bulk_g2s(sb + 2 * A_PART + B_PART, wloB + bw, B_PART, fb);
                if (++st == STAGES) { st = 0; ph ^= 1; }
            }
        }
        return;
    }

    // ---------------- consumers (warps 0-15), 32x64 warp tiles --------------
    const int warp_m = wid & 3;    // 4 x 32 rows
    const int warp_n = wid >> 2;   // 4 x 64 cols

    float acc[2][8][4];
    #pragma unroll
    for (int i = 0; i < 2; ++i)
        #pragma unroll
        for (int j = 0; j < 8; ++j)
            #pragma unroll
            for (int e = 0; e < 4; ++e)
                acc[i][j][e] = 0.f;

    // frag row byte-offsets (swizzle key recomputed from row bits: (off>>7)&7)
    uint32_t aRow[2], bRow[4];
    #pragma unroll
    for (int i = 0; i < 2; ++i) {
        int r = warp_m * 32 + i * 16 + (lane & 15);
        aRow[i] = (uint32_t)r * 128;
    }
    #pragma unroll
    for (int jj = 0; jj < 4; ++jj) {
        int r = warp_n * 64 + jj * 16 + (lane & 7) + ((lane >> 4) & 1) * 8;
        bRow[jj] = (uint32_t)r * 128;
    }
    const uint32_t ac0 = (uint32_t)(lane >> 4);        // 0/1 (k8 half, A)
    const uint32_t bc0 = (uint32_t)((lane >> 3) & 1);  // 0/1 (k8 half, B)

    int st = 0, ph = 0;
    for (int kt = 0; kt < NKT; ++kt) {
        MBARRIER_WAIT_PARITY(sFull + st * 8, ph);
        const uint32_t sb = sdyn + st * STAGE_B;
        const uint32_t ah = sb;
        const uint32_t al = sb + A_PART;
        const uint32_t bh = sb + 2 * A_PART;
        const uint32_t bl = sb + 2 * A_PART + B_PART;

        #pragma unroll
        for (int kk = 0; kk < 4; ++kk) {       // four k16 steps of BK=64
            uint32_t Ah[2][4], Al[2][4], Bf[4][4];
            const uint32_t ca = kk * 2 + ac0;
            const uint32_t cb = kk * 2 + bc0;
            #pragma unroll
            for (int i = 0; i < 2; ++i) {
                uint32_t off = aRow[i] + ((ca ^ ((aRow[i] >> 7) & 7)) << 4);
                ldsm_x4(Ah[i], ah + off);
                ldsm_x4(Al[i], al + off);
            }
            // pass 1+2: B = Bhi
            #pragma unroll
            for (int jj = 0; jj < 4; ++jj) {
                uint32_t off = bRow[jj] + ((cb ^ ((bRow[jj] >> 7) & 7)) << 4);
                ldsm_x4(Bf[jj], bh + off);
            }
            #pragma unroll
            for (int i = 0; i < 2; ++i)
                #pragma unroll
                for (int j = 0; j < 8; ++j)
                    mma16816(acc[i][j], Ah[i], &Bf[j >> 1][(j & 1) * 2]);
            #pragma unroll
            for (int i = 0; i < 2; ++i)
                #pragma unroll
                for (int j = 0; j < 8; ++j)
                    mma16816(acc[i][j], Al[i], &Bf[j >> 1][(j & 1) * 2]);
            // pass 3: B = Blo (reuse Bf registers)
            #pragma unroll
            for (int jj = 0; jj < 4; ++jj) {
                uint32_t off = bRow[jj] + ((cb ^ ((bRow[jj] >> 7) & 7)) << 4);
                ldsm_x4(Bf[jj], bl + off);
            }
            #pragma unroll
            for (int i = 0; i < 2; ++i)
                #pragma unroll
                for (int j = 0; j < 8; ++j)
                    mma16816(acc[i][j], Ah[i], &Bf[j >> 1][(j & 1) * 2]);
        }
        if (lane == 0) MBARRIER_ARRIVE(sEmpty + st * 8);
        if (++st == STAGES) { st = 0; ph ^= 1; }
    }

    // epilogue: y = x * softplus(acc + b1) * s
    #pragma unroll
    for (int i = 0; i < 2; ++i) {
        const int r0 = rbase + warp_m * 32 + i * 16 + (lane >> 2);
        const int r1 = r0 + 8;
        const float s0 = g_s[r0], s1 = g_s[r1];
        #pragma unroll
        for (int j = 0; j < 8; ++j) {
            const int c = cbase + warp_n * 64 + j * 8 + (lane & 3) * 2;
            float2 bv = *reinterpret_cast<const float2*>(b1 + c);
            float2 x0 = *reinterpret_cast<const float2*>(x + (size_t)r0 * DDIM + c);
            float2 x1 = *reinterpret_cast<const float2*>(x + (size_t)r1 * DDIM + c);
            float2 o0, o1;
            o0.x = x0.x * softplusf(acc[i][j][0] + bv.x) * s0;
            o0.y = x0.y * softplusf(acc[i][j][1] + bv.y) * s0;
            o1.x = x1.x * softplusf(acc[i][j][2] + bv.x) * s1;
            o1.y = x1.y * softplusf(acc[i][j][3] + bv.y) * s1;
            *reinterpret_cast<float2*>(y + (size_t)r0 * DDIM + c) = o0;
            *reinterpret_cast<float2*>(y + (size_t)r1 * DDIM + c) = o1;
        }
    }
}

// ---------------------------------------------------------------------------
extern "C" void kernel_launch(void* const* d_in, const int* in_sizes, int n_in,
                              void* d_out, int out_size)
{
    const float* x  = (const float*)d_in[0];
    const float* W1 = (const float*)d_in[1];
    const float* b1 = (const float*)d_in[2];
    const float* W2 = (const float*)d_in[3];
    const float* b2 = (const float*)d_in[4];
    const float* W3 = (const float*)d_in[5];
    const float* b3 = (const float*)d_in[6];
    // d_in[7] = A is mathematically dead (multiplies zero-initialized h).
    float* y = (float*)d_out;

    cudaFuncSetAttribute(gemm_kernel,
                         cudaFuncAttributeMaxDynamicSharedMemorySize, GEMM_SMEM);

    prep_kernel<<<768, 256>>>(x, W1, W2, b2, W3, b3);

    dim3 grid(DDIM / 256, TOKENS / 128);   // (4, 32) = 128 CTAs, one wave
    gemm_kernel<<<grid, 544, GEMM_SMEM>>>(x, b1, y);
}

// round 11
// speedup vs baseline: 1.0359x; 1.0359x over previous
#include <cuda_runtime.h>
#include <cuda_bf16.h>
#include <math.h>
#include <stdint.h>

#define TOKENS 4096
#define DDIM   1024

// ---------------------------------------------------------------------------
// scratch (__device__ globals; no cudaMalloc allowed)
// x/W1 hi+lo bf16, PRE-TILED into 16KB tiles (128 rows x 64 cols, SW128-swizzled)
// x: 32 mb x 16 kt = 512 tiles;  W1: 8 nb x 16 kt = 128 tiles
// ---------------------------------------------------------------------------
__device__ float g_s[TOKENS];
__device__ __align__(1024) uint4 g_xhi[512 * 1024];
__device__ __align__(1024) uint4 g_xlo[512 * 1024];
__device__ __align__(1024) uint4 g_whi[128 * 1024];
__device__ __align__(1024) uint4 g_wlo[128 * 1024];

__device__ __forceinline__ float softplusf(float z) {
    if (z > 20.0f) return z;
    return log1pf(expf(z));
}

__device__ __forceinline__ uint32_t smem_u32(const void* p) {
    uint32_t a;
    asm("{ .reg .u64 t; cvta.to.shared.u64 t, %1; cvt.u32.u64 %0, t; }"
        : "=r"(a) : "l"(p));
    return a;
}

#define MBARRIER_INIT(addr, cnt) \
    asm volatile("mbarrier.init.shared.b64 [%0], %1;" :: "r"(addr), "r"(cnt) : "memory")
#define MBARRIER_EXPECT_TX(addr, bytes) \
    asm volatile("mbarrier.arrive.expect_tx.shared.b64 _, [%0], %1;" \
        :: "r"(addr), "r"(bytes) : "memory")
#define MBARRIER_ARRIVE(addr) \
    asm volatile("mbarrier.arrive.shared.b64 _, [%0];" :: "r"(addr) : "memory")

#define MBARRIER_WAIT_PARITY(addr, parity) do { \
    uint32_t _m = (addr); uint32_t _p = (parity); uint32_t _d; \
    asm volatile("{\n\t.reg .pred p;\n\t" \
        "mbarrier.try_wait.parity.acquire.cta.shared::cta.b64 p, [%1], %2;\n\t" \
        "selp.b32 %0, 1, 0, p;\n\t}" : "=r"(_d) : "r"(_m), "r"(_p) : "memory"); \
    if (!_d) { \
        asm volatile("{\n\t.reg .pred P1;\n\t" \
            "WL_%=:\n\t" \
            "mbarrier.try_wait.parity.acquire.cta.shared::cta.b64 P1, [%0], %1, 0x989680;\n\t" \
            "@P1 bra.uni WD_%=;\n\t" \
            "bra.uni WL_%=;\n\t" \
            "WD_%=:\n\t}" :: "r"(_m), "r"(_p) : "memory"); \
    } \
} while (0)

__device__ __forceinline__ void bulk_g2s(uint32_t dst, const void* src,
                                         uint32_t bytes, uint32_t mbar) {
    asm volatile(
        "cp.async.bulk.shared::cluster.global.mbarrier::complete_tx::bytes "
        "[%0], [%1], %2, [%3];"
        :: "r"(dst), "l"(src), "r"(bytes), "r"(mbar) : "memory");
}

__device__ __forceinline__ void cp16(uint32_t dst, const void* src) {
    asm volatile("cp.async.cg.shared.global [%0], [%1], 16;"
                 :: "r"(dst), "l"(src) : "memory");
}
#define CP_COMMIT() asm volatile("cp.async.commit_group;" ::: "memory")
#define CP_WAIT1()  asm volatile("cp.async.wait_group 1;" ::: "memory")
#define CP_WAIT0()  asm volatile("cp.async.wait_group 0;" ::: "memory")

__device__ __forceinline__ void ldsm_x4(uint32_t* r, uint32_t addr) {
    asm volatile("ldmatrix.sync.aligned.m8n8.x4.shared.b16 {%0,%1,%2,%3}, [%4];"
                 : "=r"(r[0]), "=r"(r[1]), "=r"(r[2]), "=r"(r[3]) : "r"(addr));
}
__device__ __forceinline__ void mma16816(float* d, const uint32_t* a,
                                         const uint32_t* b) {
    asm volatile(
        "mma.sync.aligned.m16n8k16.row.col.f32.bf16.bf16.f32 "
        "{%0,%1,%2,%3}, {%4,%5,%6,%7}, {%8,%9}, {%0,%1,%2,%3};"
        : "+f"(d[0]), "+f"(d[1]), "+f"(d[2]), "+f"(d[3])
        : "r"(a[0]), "r"(a[1]), "r"(a[2]), "r"(a[3]), "r"(b[0]), "r"(b[1]));
}

// ---------------------------------------------------------------------------
// Kernel 0 (merged prep):
//  blocks 0..255   : s[t] — 16 tokens/block, 2-stage cp.async pipeline
//  blocks 256..767 : split x into bf16 hi/lo 128x64 tiles (SW128-pre-swizzled)
//  blocks 768..895 : split W1 likewise
// ---------------------------------------------------------------------------
__global__ __launch_bounds__(256) void prep_kernel(
    const float* __restrict__ X, const float* __restrict__ W,
    const float* __restrict__ W2, const float* __restrict__ b2,
    const float* __restrict__ W3, const float* __restrict__ b3)
{
    __shared__ float sx[2][16][68];
    __shared__ float sw[2][32][68];
    __shared__ float sout[16][33];

    const int bid = blockIdx.x;
    const int tid = threadIdx.x;

    if (bid >= 256) {
        // ------------- convert part -------------
        const int cb = bid - 256;
        const float* src;
        uint4 *dhi, *dlo;
        if (cb < 512) {
            int mb = cb >> 4, kb = cb & 15;
            src = X + (size_t)mb * 128 * DDIM + kb * 64;
            dhi = g_xhi + (size_t)cb * 1024;
            dlo = g_xlo + (size_t)cb * 1024;
        } else {
            int t = cb - 512;
            int nb = t >> 4, kb = t & 15;
            src = W + (size_t)nb * 128 * DDIM + kb * 64;
            dhi = g_whi + (size_t)t * 1024;
            dlo = g_wlo + (size_t)t * 1024;
        }
        #pragma unroll
        for (int it = 0; it < 4; ++it) {
            int c = tid + it * 256;
            int row = c >> 3, c8 = c & 7;
            const float* p = src + (size_t)row * DDIM + c8 * 8;
            float4 v0 = *reinterpret_cast<const float4*>(p);
            float4 v1 = *reinterpret_cast<const float4*>(p + 4);
            float v[8] = {v0.x, v0.y, v0.z, v0.w, v1.x, v1.y, v1.z, v1.w};
            uint32_t ph[4], pl[4];
            #pragma unroll
            for (int i = 0; i < 4; ++i) {
                __nv_bfloat16 h0 = __float2bfloat16_rn(v[2 * i]);
                __nv_bfloat16 h1 = __float2bfloat16_rn(v[2 * i + 1]);
                __nv_bfloat16 l0 = __float2bfloat16_rn(v[2 * i]     - __bfloat162float(h0));
                __nv_bfloat16 l1 = __float2bfloat16_rn(v[2 * i + 1] - __bfloat162float(h1));
                ph[i] = (uint32_t)__bfloat16_as_ushort(h0) |
                        ((uint32_t)__bfloat16_as_ushort(h1) << 16);
                pl[i] = (uint32_t)__bfloat16_as_ushort(l0) |
                        ((uint32_t)__bfloat16_as_ushort(l1) << 16);
            }
            uint32_t off = (uint32_t)(row * 128 + c8 * 16);
            off ^= ((off >> 3) & 0x70);   // SW128 swizzle, pre-applied
            dhi[off >> 4] = make_uint4(ph[0], ph[1], ph[2], ph[3]);
            dlo[off >> 4] = make_uint4(pl[0], pl[1], pl[2], pl[3]);
        }
        return;
    }

    // ------------- s part (bids 0..255): 16 tokens/block -------------------
    const int t0  = bid * 16;
    const int tok = tid & 15;
    const int g   = tid >> 4;            // 0..15, owns n = 2g, 2g+1

    const int xr = tid >> 4;             // 0..15 (x load row)
    const int xc = tid & 15;             // f4 chunk
    const int wr = tid >> 3;             // 0..31 (w load row)
    const int wc2 = (tid & 7) * 2;       // 2 f4 chunks/thread
    const float* xsrc = &X[(size_t)(t0 + xr) * DDIM];
    const float* wsrc = (wr < 16) ? &W2[(size_t)wr * DDIM]
                                  : &W3[(size_t)(wr - 16) * DDIM];

    #define S_LOAD(st, kt) do {                                             \
        int _k0 = (kt) * 64;                                                \
        cp16(smem_u32(&sx[st][xr][xc * 4]), xsrc + _k0 + xc * 4);           \
        cp16(smem_u32(&sw[st][wr][wc2 * 4]),       wsrc + _k0 + wc2 * 4);   \
        cp16(smem_u32(&sw[st][wr][(wc2 + 1) * 4]), wsrc + _k0 + (wc2 + 1) * 4); \
        CP_COMMIT();                                                        \
    } while (0)

    float acc[2] = {0.f, 0.f};

    S_LOAD(0, 0);
    S_LOAD(1, 1);

    for (int kt = 0; kt < 16; ++kt) {
        const int st = kt & 1;
        if (kt == 15) { CP_WAIT0(); } else { CP_WAIT1(); }
        __syncthreads();
        #pragma unroll
        for (int k4 = 0; k4 < 16; ++k4) {
            float4 xv = *reinterpret_cast<const float4*>(&sx[st][tok][k4 * 4]);
            #pragma unroll
            for (int j = 0; j < 2; ++j) {
                float4 wv = *reinterpret_cast<const float4*>(&sw[st][g * 2 + j][k4 * 4]);
                acc[j] += xv.x * wv.x + xv.y * wv.y + xv.z * wv.z + xv.w * wv.w;
            }
        }
        __syncthreads();
        if (kt + 2 < 16) S_LOAD(st, kt + 2);
    }

    #pragma unroll
    for (int j = 0; j < 2; ++j) sout[tok][g * 2 + j] = acc[j];
    __syncthreads();

    if (tid < 16) {
        float s = 0.f;
        #pragma unroll
        for (int n = 0; n < 16; ++n)
            s += (sout[tid][n] + b2[n]) * (sout[tid][16 + n] + b3[n]);
        g_s[t0 + tid] = s;
    }
}

// ---------------------------------------------------------------------------
// Kernel 1: mma.sync bf16x3 GEMM, cp.async.bulk-fed, fused epilogue.
//   D = xhi@whi^T + xhi@wlo^T + xlo@whi^T; y = x * softplus(D + b1) * s
// BM=BN=128, BK=64, 3-stage bulk pipeline, 544 threads:
//   warps 0-15 compute (32x32 tiles, 4 warps/SMSP for TLP), warp 16 = producer.
// (R9 configuration — best measured: GEMM 69.6us, tensor 60.5%)
// ---------------------------------------------------------------------------
#define NKT 16                    // 1024 / 64
#define STAGES 3
#define PART_B 16384              // one 128x64 bf16 tile
#define STAGE_B (4 * PART_B)      // Ahi, Alo, Bhi, Blo = 64KB
#define GEMM_SMEM (STAGES * STAGE_B)   // 196608

__global__ __launch_bounds__(544, 1) void gemm_kernel(
    const float* __restrict__ x,
    const float* __restrict__ b1,
    float* __restrict__ y)
{
    extern __shared__ __align__(1024) char smem[];
    __shared__ __align__(8) uint64_t mbar[2 * STAGES];  // full[0..2], empty[0..2]

    const uint32_t sdyn = smem_u32(smem);
    const uint32_t sFull  = smem_u32(&mbar[0]);
    const uint32_t sEmpty = smem_u32(&mbar[STAGES]);

    const int tid  = threadIdx.x;
    const int wid  = tid >> 5;
    const int lane = tid & 31;
    const int nb = blockIdx.x;          // 0..7
    const int mb = blockIdx.y;          // 0..31
    const int rbase = mb * 128;
    const int cbase = nb * 128;

    if (tid == 0) {
        #pragma unroll
        for (int s = 0; s < STAGES; ++s) {
            MBARRIER_INIT(sFull  + s * 8, 1);
            MBARRIER_INIT(sEmpty + s * 8, 16);
        }
    }
    __syncthreads();

    if (wid == 16) {
        // ---------------- producer ----------------
        if (lane == 0) {
            const char* xhiB = (const char*)g_xhi;
            const char* xloB = (const char*)g_xlo;
            const char* whiB = (const char*)g_whi;
            const char* wloB = (const char*)g_wlo;
            int st = 0, ph = 1;
            for (int kt = 0; kt < NKT; ++kt) {
                MBARRIER_WAIT_PARITY(sEmpty + st * 8, ph);
                uint32_t fb = sFull + st * 8;
                MBARRIER_EXPECT_TX(fb, STAGE_B);
                uint32_t sb = sdyn + st * STAGE_B;
                size_t ax = ((size_t)(mb * NKT + kt)) * PART_B;
                size_t bw = ((size_t)(nb * NKT + kt)) * PART_B;
                bulk_g2s(sb + 0 * PART_B, xhiB + ax, PART_B, fb);
                bulk_g2s(sb + 1 * PART_B, xloB + ax, PART_B, fb);
                bulk_g2s(sb + 2 * PART_B, whiB + bw, PART_B, fb);
                bulk_g2s(sb + 3 * PART_B, wloB + bw, PART_B, fb);
                if (++st == STAGES) { st = 0; ph ^= 1; }
            }
        }
        return;
    }

    // ---------------- consumers (warps 0-15), 32x32 warp tiles ----------------
    const int warp_m = wid & 3;    // row group: 32 rows
    const int warp_n = wid >> 2;   // col group: 32 cols

    float acc[2][4][4];
    #pragma unroll
    for (int i = 0; i < 2; ++i)
        #pragma unroll
        for (int j = 0; j < 4; ++j)
            #pragma unroll
            for (int e = 0; e < 4; ++e)
                acc[i][j][e] = 0.f;

    // A frag addresses: i in {0,1} (two m16 tiles)
    uint32_t aRow[2], aSw[2];
    #pragma unroll
    for (int i = 0; i < 2; ++i) {
        int r = warp_m * 32 + i * 16 + (lane & 15);
        aRow[i] = (uint32_t)r * 128;
        aSw[i]  = (uint32_t)(r & 7);
    }
    // B frag addresses via ldsm_x4: jj in {0,1}, each yields 2 n8 frags
    uint32_t bRow[2], bSw[2];
    #pragma unroll
    for (int jj = 0; jj < 2; ++jj) {
        int r = warp_n * 32 + jj * 16 + (lane & 7) + ((lane >> 4) & 1) * 8;
        bRow[jj] = (uint32_t)r * 128;
        bSw[jj]  = (uint32_t)(r & 7);
    }
    const uint32_t ac0 = (uint32_t)(lane >> 4);        // 0/1 (k8 half for A)
    const uint32_t bc0 = (uint32_t)((lane >> 3) & 1);  // 0/1 (k8 half for B)

    int st = 0, ph = 0;
    for (int kt = 0; kt < NKT; ++kt) {
        MBARRIER_WAIT_PARITY(sFull + st * 8, ph);
        const uint32_t sb = sdyn + st * STAGE_B;
        const uint32_t ah = sb + 0 * PART_B;
        const uint32_t al = sb + 1 * PART_B;
        const uint32_t bh = sb + 2 * PART_B;
        const uint32_t bl = sb + 3 * PART_B;

        #pragma unroll
        for (int kk = 0; kk < 4; ++kk) {       // four k16 steps of BK=64
            uint32_t Ah[2][4], Al[2][4], Bh[2][4], Bl[2][4];
            const uint32_t ca = kk * 2 + ac0;
            const uint32_t cb = kk * 2 + bc0;
            #pragma unroll
            for (int i = 0; i < 2; ++i) {
                uint32_t off = aRow[i] + ((ca ^ aSw[i]) << 4);
                ldsm_x4(Ah[i], ah + off);
                ldsm_x4(Al[i], al + off);
            }
            #pragma unroll
            for (int jj = 0; jj < 2; ++jj) {
                uint32_t off = bRow[jj] + ((cb ^ bSw[jj]) << 4);
                ldsm_x4(Bh[jj], bh + off);
                ldsm_x4(Bl[jj], bl + off);
            }
            // term-major: 8 MMAs per term, reuse distance 8
            #pragma unroll
            for (int i = 0; i < 2; ++i)
                #pragma unroll
                for (int j = 0; j < 4; ++j)
                    mma16816(acc[i][j], Ah[i], &Bh[j >> 1][(j & 1) * 2]);
            #pragma unroll
            for (int i = 0; i < 2; ++i)
                #pragma unroll
                for (int j = 0; j < 4; ++j)
                    mma16816(acc[i][j], Ah[i], &Bl[j >> 1][(j & 1) * 2]);
            #pragma unroll
            for (int i = 0; i < 2; ++i)
                #pragma unroll
                for (int j = 0; j < 4; ++j)
                    mma16816(acc[i][j], Al[i], &Bh[j >> 1][(j & 1) * 2]);
        }
        if (lane == 0) MBARRIER_ARRIVE(sEmpty + st * 8);
        if (++st == STAGES) { st = 0; ph ^= 1; }
    }

    // epilogue: y = x * softplus(acc + b1) * s
    #pragma unroll
    for (int i = 0; i < 2; ++i) {
        const int r0 = rbase + warp_m * 32 + i * 16 + (lane >> 2);
        const int r1 = r0 + 8;
        const float s0 = g_s[r0], s1 = g_s[r1];
        #pragma unroll
        for (int j = 0; j < 4; ++j) {
            const int c = cbase + warp_n * 32 + j * 8 + (lane & 3) * 2;
            float2 bv = *reinterpret_cast<const float2*>(b1 + c);
            float2 x0 = *reinterpret_cast<const float2*>(x + (size_t)r0 * DDIM + c);
            float2 x1 = *reinterpret_cast<const float2*>(x + (size_t)r1 * DDIM + c);
            float2 o0, o1;
            o0.x = x0.x * softplusf(acc[i][j][0] + bv.x) * s0;
            o0.y = x0.y * softplusf(acc[i][j][1] + bv.y) * s0;
            o1.x = x1.x * softplusf(acc[i][j][2] + bv.x) * s1;
            o1.y = x1.y * softplusf(acc[i][j][3] + bv.y) * s1;
            *reinterpret_cast<float2*>(y + (size_t)r0 * DDIM + c) = o0;
            *reinterpret_cast<float2*>(y + (size_t)r1 * DDIM + c) = o1;
        }
    }
}

// ---------------------------------------------------------------------------
extern "C" void kernel_launch(void* const* d_in, const int* in_sizes, int n_in,
                              void* d_out, int out_size)
{
    const float* x  = (const float*)d_in[0];
    const float* W1 = (const float*)d_in[1];
    const float* b1 = (const float*)d_in[2];
    const float* W2 = (const float*)d_in[3];
    const float* b2 = (const float*)d_in[4];
    const float* W3 = (const float*)d_in[5];
    const float* b3 = (const float*)d_in[6];
    // d_in[7] = A is mathematically dead (multiplies zero-initialized h).
    float* y = (float*)d_out;

    cudaFuncSetAttribute(gemm_kernel,
                         cudaFuncAttributeMaxDynamicSharedMemorySize, GEMM_SMEM);

    prep_kernel<<<896, 256>>>(x, W1, W2, b2, W3, b3);

    dim3 grid(DDIM / 128, TOKENS / 128);   // (8, 32)
    gemm_kernel<<<grid, 544, GEMM_SMEM>>>(x, b1, y);
}

// round 12
// speedup vs baseline: 1.2565x; 1.2130x over previous
#include <cuda_runtime.h>
#include <cuda_fp16.h>
#include <math.h>
#include <stdint.h>

#define TOKENS 4096
#define DDIM   1024

// ---------------------------------------------------------------------------
// scratch (__device__ globals; no cudaMalloc allowed)
// fp16 2-term scheme: x = xhi + xlo (both fp16), W ~ whi (fp16)
// tiles: 128 rows x 64 cols fp16 = 16KB, SW128-pre-swizzled
// x: 32 mb x 16 kt = 512 tiles;  W1: 8 nb x 16 kt = 128 tiles
// ---------------------------------------------------------------------------
__device__ float g_s[TOKENS];
__device__ __align__(1024) uint4 g_xhi[512 * 1024];
__device__ __align__(1024) uint4 g_xlo[512 * 1024];
__device__ __align__(1024) uint4 g_whi[128 * 1024];

__device__ __forceinline__ float softplusf(float z) {
    if (z > 20.0f) return z;
    return log1pf(expf(z));
}

__device__ __forceinline__ uint32_t smem_u32(const void* p) {
    uint32_t a;
    asm("{ .reg .u64 t; cvta.to.shared.u64 t, %1; cvt.u32.u64 %0, t; }"
        : "=r"(a) : "l"(p));
    return a;
}

#define MBARRIER_INIT(addr, cnt) \
    asm volatile("mbarrier.init.shared.b64 [%0], %1;" :: "r"(addr), "r"(cnt) : "memory")
#define MBARRIER_EXPECT_TX(addr, bytes) \
    asm volatile("mbarrier.arrive.expect_tx.shared.b64 _, [%0], %1;" \
        :: "r"(addr), "r"(bytes) : "memory")
#define MBARRIER_ARRIVE(addr) \
    asm volatile("mbarrier.arrive.shared.b64 _, [%0];" :: "r"(addr) : "memory")

#define MBARRIER_WAIT_PARITY(addr, parity) do { \
    uint32_t _m = (addr); uint32_t _p = (parity); uint32_t _d; \
    asm volatile("{\n\t.reg .pred p;\n\t" \
        "mbarrier.try_wait.parity.acquire.cta.shared::cta.b64 p, [%1], %2;\n\t" \
        "selp.b32 %0, 1, 0, p;\n\t}" : "=r"(_d) : "r"(_m), "r"(_p) : "memory"); \
    if (!_d) { \
        asm volatile("{\n\t.reg .pred P1;\n\t" \
            "WL_%=:\n\t" \
            "mbarrier.try_wait.parity.acquire.cta.shared::cta.b64 P1, [%0], %1, 0x989680;\n\t" \
            "@P1 bra.uni WD_%=;\n\t" \
            "bra.uni WL_%=;\n\t" \
            "WD_%=:\n\t}" :: "r"(_m), "r"(_p) : "memory"); \
    } \
} while (0)

__device__ __forceinline__ void bulk_g2s(uint32_t dst, const void* src,
                                         uint32_t bytes, uint32_t mbar) {
    asm volatile(
        "cp.async.bulk.shared::cluster.global.mbarrier::complete_tx::bytes "
        "[%0], [%1], %2, [%3];"
        :: "r"(dst), "l"(src), "r"(bytes), "r"(mbar) : "memory");
}

__device__ __forceinline__ void cp16(uint32_t dst, const void* src) {
    asm volatile("cp.async.cg.shared.global [%0], [%1], 16;"
                 :: "r"(dst), "l"(src) : "memory");
}
#define CP_COMMIT() asm volatile("cp.async.commit_group;" ::: "memory")
#define CP_WAIT1()  asm volatile("cp.async.wait_group 1;" ::: "memory")
#define CP_WAIT0()  asm volatile("cp.async.wait_group 0;" ::: "memory")

__device__ __forceinline__ void ldsm_x4(uint32_t* r, uint32_t addr) {
    asm volatile("ldmatrix.sync.aligned.m8n8.x4.shared.b16 {%0,%1,%2,%3}, [%4];"
                 : "=r"(r[0]), "=r"(r[1]), "=r"(r[2]), "=r"(r[3]) : "r"(addr));
}
__device__ __forceinline__ void mma16816h(float* d, const uint32_t* a,
                                          const uint32_t* b) {
    asm volatile(
        "mma.sync.aligned.m16n8k16.row.col.f32.f16.f16.f32 "
        "{%0,%1,%2,%3}, {%4,%5,%6,%7}, {%8,%9}, {%0,%1,%2,%3};"
        : "+f"(d[0]), "+f"(d[1]), "+f"(d[2]), "+f"(d[3])
        : "r"(a[0]), "r"(a[1]), "r"(a[2]), "r"(a[3]), "r"(b[0]), "r"(b[1]));
}

// ---------------------------------------------------------------------------
// Kernel 0 (merged prep):
//  blocks 0..255   : s[t] — 16 tokens/block, 2-stage cp.async pipeline (fp32)
//  blocks 256..767 : split x into fp16 hi+lo 128x64 tiles (SW128-pre-swizzled)
//  blocks 768..895 : downcast W1 to fp16 tiles (hi only)
// ---------------------------------------------------------------------------
__global__ __launch_bounds__(256) void prep_kernel(
    const float* __restrict__ X, const float* __restrict__ W,
    const float* __restrict__ W2, const float* __restrict__ b2,
    const float* __restrict__ W3, const float* __restrict__ b3)
{
    __shared__ float sx[2][16][68];
    __shared__ float sw[2][32][68];
    __shared__ float sout[16][33];

    const int bid = blockIdx.x;
    const int tid = threadIdx.x;

    if (bid >= 256) {
        // ------------- convert part -------------
        const int cb = bid - 256;
        const float* src;
        uint4 *dhi, *dlo;
        if (cb < 512) {
            int mb = cb >> 4, kb = cb & 15;
            src = X + (size_t)mb * 128 * DDIM + kb * 64;
            dhi = g_xhi + (size_t)cb * 1024;
            dlo = g_xlo + (size_t)cb * 1024;
        } else {
            int t = cb - 512;
            int nb = t >> 4, kb = t & 15;
            src = W + (size_t)nb * 128 * DDIM + kb * 64;
            dhi = g_whi + (size_t)t * 1024;
            dlo = nullptr;
        }
        #pragma unroll
        for (int it = 0; it < 4; ++it) {
            int c = tid + it * 256;
            int row = c >> 3, c8 = c & 7;
            const float* p = src + (size_t)row * DDIM + c8 * 8;
            float4 v0 = *reinterpret_cast<const float4*>(p);
            float4 v1 = *reinterpret_cast<const float4*>(p + 4);
            float v[8] = {v0.x, v0.y, v0.z, v0.w, v1.x, v1.y, v1.z, v1.w};
            uint32_t ph[4], pl[4];
            #pragma unroll
            for (int i = 0; i < 4; ++i) {
                __half h0 = __float2half_rn(v[2 * i]);
                __half h1 = __float2half_rn(v[2 * i + 1]);
                __half l0 = __float2half_rn(v[2 * i]     - __half2float(h0));
                __half l1 = __float2half_rn(v[2 * i + 1] - __half2float(h1));
                ph[i] = (uint32_t)__half_as_ushort(h0) |
                        ((uint32_t)__half_as_ushort(h1) << 16);
                pl[i] = (uint32_t)__half_as_ushort(l0) |
                        ((uint32_t)__half_as_ushort(l1) << 16);
            }
            uint32_t off = (uint32_t)(row * 128 + c8 * 16);
            off ^= ((off >> 3) & 0x70);   // SW128 swizzle, pre-applied
            dhi[off >> 4] = make_uint4(ph[0], ph[1], ph[2], ph[3]);
            if (dlo) dlo[off >> 4] = make_uint4(pl[0], pl[1], pl[2], pl[3]);
        }
        return;
    }

    // ------------- s part (bids 0..255): 16 tokens/block -------------------
    const int t0  = bid * 16;
    const int tok = tid & 15;
    const int g   = tid >> 4;            // 0..15, owns n = 2g, 2g+1

    const int xr = tid >> 4;             // 0..15 (x load row)
    const int xc = tid & 15;             // f4 chunk
    const int wr = tid >> 3;             // 0..31 (w load row)
    const int wc2 = (tid & 7) * 2;       // 2 f4 chunks/thread
    const float* xsrc = &X[(size_t)(t0 + xr) * DDIM];
    const float* wsrc = (wr < 16) ? &W2[(size_t)wr * DDIM]
                                  : &W3[(size_t)(wr - 16) * DDIM];

    #define S_LOAD(st, kt) do {                                             \
        int _k0 = (kt) * 64;                                                \
        cp16(smem_u32(&sx[st][xr][xc * 4]), xsrc + _k0 + xc * 4);           \
        cp16(smem_u32(&sw[st][wr][wc2 * 4]),       wsrc + _k0 + wc2 * 4);   \
        cp16(smem_u32(&sw[st][wr][(wc2 + 1) * 4]), wsrc + _k0 + (wc2 + 1) * 4); \
        CP_COMMIT();                                                        \
    } while (0)

    float acc[2] = {0.f, 0.f};

    S_LOAD(0, 0);
    S_LOAD(1, 1);

    for (int kt = 0; kt < 16; ++kt) {
        const int st = kt & 1;
        if (kt == 15) { CP_WAIT0(); } else { CP_WAIT1(); }
        __syncthreads();
        #pragma unroll
        for (int k4 = 0; k4 < 16; ++k4) {
            float4 xv = *reinterpret_cast<const float4*>(&sx[st][tok][k4 * 4]);
            #pragma unroll
            for (int j = 0; j < 2; ++j) {
                float4 wv = *reinterpret_cast<const float4*>(&sw[st][g * 2 + j][k4 * 4]);
                acc[j] += xv.x * wv.x + xv.y * wv.y + xv.z * wv.z + xv.w * wv.w;
            }
        }
        __syncthreads();
        if (kt + 2 < 16) S_LOAD(st, kt + 2);
    }

    #pragma unroll
    for (int j = 0; j < 2; ++j) sout[tok][g * 2 + j] = acc[j];
    __syncthreads();

    if (tid < 16) {
        float s = 0.f;
        #pragma unroll
        for (int n = 0; n < 16; ++n)
            s += (sout[tid][n] + b2[n]) * (sout[tid][16 + n] + b3[n]);
        g_s[t0 + tid] = s;
    }
}

// ---------------------------------------------------------------------------
// Kernel 1: mma.sync fp16 2-term GEMM, cp.async.bulk-fed, fused epilogue.
//   D = xhi@whi^T + xlo@whi^T  (= x@fp16(W1)^T to fp32-grade accuracy)
//   y = x * softplus(D + b1) * s
// BM=BN=128, BK=64, 4-stage bulk pipeline (48KB/stage), 544 threads:
//   warps 0-15 compute (32x32 tiles, 4 warps/SMSP), warp 16 = producer.
// ---------------------------------------------------------------------------
#define NKT 16                    // 1024 / 64
#define STAGES 4
#define PART_B 16384              // one 128x64 fp16 tile
#define STAGE_B (3 * PART_B)      // Ahi, Alo, B = 48KB
#define GEMM_SMEM (STAGES * STAGE_B)   // 196608

__global__ __launch_bounds__(544, 1) void gemm_kernel(
    const float* __restrict__ x,
    const float* __restrict__ b1,
    float* __restrict__ y)
{
    extern __shared__ __align__(1024) char smem[];
    __shared__ __align__(8) uint64_t mbar[2 * STAGES];  // full[0..3], empty[0..3]

    const uint32_t sdyn = smem_u32(smem);
    const uint32_t sFull  = smem_u32(&mbar[0]);
    const uint32_t sEmpty = smem_u32(&mbar[STAGES]);

    const int tid  = threadIdx.x;
    const int wid  = tid >> 5;
    const int lane = tid & 31;
    const int nb = blockIdx.x;          // 0..7
    const int mb = blockIdx.y;          // 0..31
    const int rbase = mb * 128;
    const int cbase = nb * 128;

    if (tid == 0) {
        #pragma unroll
        for (int s = 0; s < STAGES; ++s) {
            MBARRIER_INIT(sFull  + s * 8, 1);
            MBARRIER_INIT(sEmpty + s * 8, 16);
        }
    }
    __syncthreads();

    if (wid == 16) {
        // ---------------- producer ----------------
        if (lane == 0) {
            const char* xhiB = (const char*)g_xhi;
            const char* xloB = (const char*)g_xlo;
            const char* whiB = (const char*)g_whi;
            int st = 0, ph = 1;
            for (int kt = 0; kt < NKT; ++kt) {
                MBARRIER_WAIT_PARITY(sEmpty + st * 8, ph);
                uint32_t fb = sFull + st * 8;
                MBARRIER_EXPECT_TX(fb, STAGE_B);
                uint32_t sb = sdyn + st * STAGE_B;
                size_t ax = ((size_t)(mb * NKT + kt)) * PART_B;
                size_t bw = ((size_t)(nb * NKT + kt)) * PART_B;
                bulk_g2s(sb + 0 * PART_B, xhiB + ax, PART_B, fb);
                bulk_g2s(sb + 1 * PART_B, xloB + ax, PART_B, fb);
                bulk_g2s(sb + 2 * PART_B, whiB + bw, PART_B, fb);
                if (++st == STAGES) { st = 0; ph ^= 1; }
            }
        }
        return;
    }

    // ---------------- consumers (warps 0-15), 32x32 warp tiles ----------------
    const int warp_m = wid & 3;    // row group: 32 rows
    const int warp_n = wid >> 2;   // col group: 32 cols

    float acc[2][4][4];
    #pragma unroll
    for (int i = 0; i < 2; ++i)
        #pragma unroll
        for (int j = 0; j < 4; ++j)
            #pragma unroll
            for (int e = 0; e < 4; ++e)
                acc[i][j][e] = 0.f;

    // A frag addresses: i in {0,1} (two m16 tiles)
    uint32_t aRow[2], aSw[2];
    #pragma unroll
    for (int i = 0; i < 2; ++i) {
        int r = warp_m * 32 + i * 16 + (lane & 15);
        aRow[i] = (uint32_t)r * 128;
        aSw[i]  = (uint32_t)(r & 7);
    }
    // B frag addresses via ldsm_x4: jj in {0,1}, each yields 2 n8 frags
    uint32_t bRow[2], bSw[2];
    #pragma unroll
    for (int jj = 0; jj < 2; ++jj) {
        int r = warp_n * 32 + jj * 16 + (lane & 7) + ((lane >> 4) & 1) * 8;
        bRow[jj] = (uint32_t)r * 128;
        bSw[jj]  = (uint32_t)(r & 7);
    }
    const uint32_t ac0 = (uint32_t)(lane >> 4);        // 0/1 (k8 half for A)
    const uint32_t bc0 = (uint32_t)((lane >> 3) & 1);  // 0/1 (k8 half for B)

    int st = 0, ph = 0;
    for (int kt = 0; kt < NKT; ++kt) {
        MBARRIER_WAIT_PARITY(sFull + st * 8, ph);
        const uint32_t sb = sdyn + st * STAGE_B;
        const uint32_t ah = sb + 0 * PART_B;
        const uint32_t al = sb + 1 * PART_B;
        const uint32_t bh = sb + 2 * PART_B;

        #pragma unroll
        for (int kk = 0; kk < 4; ++kk) {       // four k16 steps of BK=64
            uint32_t Ah[2][4], Al[2][4], Bf[2][4];
            const uint32_t ca = kk * 2 + ac0;
            const uint32_t cb = kk * 2 + bc0;
            #pragma unroll
            for (int i = 0; i < 2; ++i) {
                uint32_t off = aRow[i] + ((ca ^ aSw[i]) << 4);
                ldsm_x4(Ah[i], ah + off);
                ldsm_x4(Al[i], al + off);
            }
            #pragma unroll
            for (int jj = 0; jj < 2; ++jj) {
                uint32_t off = bRow[jj] + ((cb ^ bSw[jj]) << 4);
                ldsm_x4(Bf[jj], bh + off);
            }
            // term-major: 8 MMAs per term, reuse distance 8
            #pragma unroll
            for (int i = 0; i < 2; ++i)
                #pragma unroll
                for (int j = 0; j < 4; ++j)
                    mma16816h(acc[i][j], Ah[i], &Bf[j >> 1][(j & 1) * 2]);
            #pragma unroll
            for (int i = 0; i < 2; ++i)
                #pragma unroll
                for (int j = 0; j < 4; ++j)
                    mma16816h(acc[i][j], Al[i], &Bf[j >> 1][(j & 1) * 2]);
        }
        if (lane == 0) MBARRIER_ARRIVE(sEmpty + st * 8);
        if (++st == STAGES) { st = 0; ph ^= 1; }
    }

    // epilogue: y = x * softplus(acc + b1) * s
    #pragma unroll
    for (int i = 0; i < 2; ++i) {
        const int r0 = rbase + warp_m * 32 + i * 16 + (lane >> 2);
        const int r1 = r0 + 8;
        const float s0 = g_s[r0], s1 = g_s[r1];
        #pragma unroll
        for (int j = 0; j < 4; ++j) {
            const int c = cbase + warp_n * 32 + j * 8 + (lane & 3) * 2;
            float2 bv = *reinterpret_cast<const float2*>(b1 + c);
            float2 x0 = *reinterpret_cast<const float2*>(x + (size_t)r0 * DDIM + c);
            float2 x1 = *reinterpret_cast<const float2*>(x + (size_t)r1 * DDIM + c);
            float2 o0, o1;
            o0.x = x0.x * softplusf(acc[i][j][0] + bv.x) * s0;
            o0.y = x0.y * softplusf(acc[i][j][1] + bv.y) * s0;
            o1.x = x1.x * softplusf(acc[i][j][2] + bv.x) * s1;
            o1.y = x1.y * softplusf(acc[i][j][3] + bv.y) * s1;
            *reinterpret_cast<float2*>(y + (size_t)r0 * DDIM + c) = o0;
            *reinterpret_cast<float2*>(y + (size_t)r1 * DDIM + c) = o1;
        }
    }
}

// ---------------------------------------------------------------------------
extern "C" void kernel_launch(void* const* d_in, const int* in_sizes, int n_in,
                              void* d_out, int out_size)
{
    const float* x  = (const float*)d_in[0];
    const float* W1 = (const float*)d_in[1];
    const float* b1 = (const float*)d_in[2];
    const float* W2 = (const float*)d_in[3];
    const float* b2 = (const float*)d_in[4];
    const float* W3 = (const float*)d_in[5];
    const float* b3 = (const float*)d_in[6];
    // d_in[7] = A is mathematically dead (multiplies zero-initialized h).
    float* y = (float*)d_out;

    cudaFuncSetAttribute(gemm_kernel,
                         cudaFuncAttributeMaxDynamicSharedMemorySize, GEMM_SMEM);

    prep_kernel<<<896, 256>>>(x, W1, W2, b2, W3, b3);

    dim3 grid(DDIM / 128, TOKENS / 128);   // (8, 32)
    gemm_kernel<<<grid, 544, GEMM_SMEM>>>(x, b1, y);
}

// round 13
// speedup vs baseline: 1.5686x; 1.2483x over previous
#include <cuda_runtime.h>
#include <cuda_fp16.h>
#include <math.h>
#include <stdint.h>

#define TOKENS 4096
#define DDIM   1024

// ---------------------------------------------------------------------------
// scratch (__device__ globals; no cudaMalloc allowed)
// fp16 1-term scheme: x ~ xhi (fp16), W ~ whi (fp16)
// tiles: 128 rows x 64 cols fp16 = 16KB, SW128-pre-swizzled
// x: 32 mb x 16 kt = 512 tiles;  W1: 8 nb x 16 kt = 128 tiles
// ---------------------------------------------------------------------------
__device__ float g_s[TOKENS];
__device__ __align__(1024) uint4 g_xhi[512 * 1024];
__device__ __align__(1024) uint4 g_whi[128 * 1024];

__device__ __forceinline__ float softplusf(float z) {
    if (z > 20.0f) return z;
    return log1pf(expf(z));
}

__device__ __forceinline__ uint32_t smem_u32(const void* p) {
    uint32_t a;
    asm("{ .reg .u64 t; cvta.to.shared.u64 t, %1; cvt.u32.u64 %0, t; }"
        : "=r"(a) : "l"(p));
    return a;
}

#define MBARRIER_INIT(addr, cnt) \
    asm volatile("mbarrier.init.shared.b64 [%0], %1;" :: "r"(addr), "r"(cnt) : "memory")
#define MBARRIER_EXPECT_TX(addr, bytes) \
    asm volatile("mbarrier.arrive.expect_tx.shared.b64 _, [%0], %1;" \
        :: "r"(addr), "r"(bytes) : "memory")
#define MBARRIER_ARRIVE(addr) \
    asm volatile("mbarrier.arrive.shared.b64 _, [%0];" :: "r"(addr) : "memory")

#define MBARRIER_WAIT_PARITY(addr, parity) do { \
    uint32_t _m = (addr); uint32_t _p = (parity); uint32_t _d; \
    asm volatile("{\n\t.reg .pred p;\n\t" \
        "mbarrier.try_wait.parity.acquire.cta.shared::cta.b64 p, [%1], %2;\n\t" \
        "selp.b32 %0, 1, 0, p;\n\t}" : "=r"(_d) : "r"(_m), "r"(_p) : "memory"); \
    if (!_d) { \
        asm volatile("{\n\t.reg .pred P1;\n\t" \
            "WL_%=:\n\t" \
            "mbarrier.try_wait.parity.acquire.cta.shared::cta.b64 P1, [%0], %1, 0x989680;\n\t" \
            "@P1 bra.uni WD_%=;\n\t" \
            "bra.uni WL_%=;\n\t" \
            "WD_%=:\n\t}" :: "r"(_m), "r"(_p) : "memory"); \
    } \
} while (0)

__device__ __forceinline__ void bulk_g2s(uint32_t dst, const void* src,
                                         uint32_t bytes, uint32_t mbar) {
    asm volatile(
        "cp.async.bulk.shared::cluster.global.mbarrier::complete_tx::bytes "
        "[%0], [%1], %2, [%3];"
        :: "r"(dst), "l"(src), "r"(bytes), "r"(mbar) : "memory");
}

__device__ __forceinline__ void cp16(uint32_t dst, const void* src) {
    asm volatile("cp.async.cg.shared.global [%0], [%1], 16;"
                 :: "r"(dst), "l"(src) : "memory");
}
#define CP_COMMIT() asm volatile("cp.async.commit_group;" ::: "memory")
#define CP_WAIT1()  asm volatile("cp.async.wait_group 1;" ::: "memory")
#define CP_WAIT0()  asm volatile("cp.async.wait_group 0;" ::: "memory")

__device__ __forceinline__ void ldsm_x4(uint32_t* r, uint32_t addr) {
    asm volatile("ldmatrix.sync.aligned.m8n8.x4.shared.b16 {%0,%1,%2,%3}, [%4];"
                 : "=r"(r[0]), "=r"(r[1]), "=r"(r[2]), "=r"(r[3]) : "r"(addr));
}
__device__ __forceinline__ void mma16816h(float* d, const uint32_t* a,
                                          const uint32_t* b) {
    asm volatile(
        "mma.sync.aligned.m16n8k16.row.col.f32.f16.f16.f32 "
        "{%0,%1,%2,%3}, {%4,%5,%6,%7}, {%8,%9}, {%0,%1,%2,%3};"
        : "+f"(d[0]), "+f"(d[1]), "+f"(d[2]), "+f"(d[3])
        : "r"(a[0]), "r"(a[1]), "r"(a[2]), "r"(a[3]), "r"(b[0]), "r"(b[1]));
}

// ---------------------------------------------------------------------------
// Kernel 0 (merged prep):
//  blocks 0..255   : s[t] — 16 tokens/block, 2-stage cp.async pipeline (fp32)
//  blocks 256..767 : downcast x to fp16 128x64 tiles (SW128-pre-swizzled)
//  blocks 768..895 : downcast W1 likewise
// ---------------------------------------------------------------------------
__global__ __launch_bounds__(256) void prep_kernel(
    const float* __restrict__ X, const float* __restrict__ W,
    const float* __restrict__ W2, const float* __restrict__ b2,
    const float* __restrict__ W3, const float* __restrict__ b3)
{
    __shared__ float sx[2][16][68];
    __shared__ float sw[2][32][68];
    __shared__ float sout[16][33];

    const int bid = blockIdx.x;
    const int tid = threadIdx.x;

    if (bid >= 256) {
        // ------------- convert part (hi only) -------------
        const int cb = bid - 256;
        const float* src;
        uint4* dhi;
        if (cb < 512) {
            int mb = cb >> 4, kb = cb & 15;
            src = X + (size_t)mb * 128 * DDIM + kb * 64;
            dhi = g_xhi + (size_t)cb * 1024;
        } else {
            int t = cb - 512;
            int nb = t >> 4, kb = t & 15;
            src = W + (size_t)nb * 128 * DDIM + kb * 64;
            dhi = g_whi + (size_t)t * 1024;
        }
        #pragma unroll
        for (int it = 0; it < 4; ++it) {
            int c = tid + it * 256;
            int row = c >> 3, c8 = c & 7;
            const float* p = src + (size_t)row * DDIM + c8 * 8;
            float4 v0 = *reinterpret_cast<const float4*>(p);
            float4 v1 = *reinterpret_cast<const float4*>(p + 4);
            float v[8] = {v0.x, v0.y, v0.z, v0.w, v1.x, v1.y, v1.z, v1.w};
            uint32_t ph[4];
            #pragma unroll
            for (int i = 0; i < 4; ++i) {
                __half h0 = __float2half_rn(v[2 * i]);
                __half h1 = __float2half_rn(v[2 * i + 1]);
                ph[i] = (uint32_t)__half_as_ushort(h0) |
                        ((uint32_t)__half_as_ushort(h1) << 16);
            }
            uint32_t off = (uint32_t)(row * 128 + c8 * 16);
            off ^= ((off >> 3) & 0x70);   // SW128 swizzle, pre-applied
            dhi[off >> 4] = make_uint4(ph[0], ph[1], ph[2], ph[3]);
        }
        return;
    }

    // ------------- s part (bids 0..255): 16 tokens/block -------------------
    const int t0  = bid * 16;
    const int tok = tid & 15;
    const int g   = tid >> 4;            // 0..15, owns n = 2g, 2g+1

    const int xr = tid >> 4;             // 0..15 (x load row)
    const int xc = tid & 15;             // f4 chunk
    const int wr = tid >> 3;             // 0..31 (w load row)
    const int wc2 = (tid & 7) * 2;       // 2 f4 chunks/thread
    const float* xsrc = &X[(size_t)(t0 + xr) * DDIM];
    const float* wsrc = (wr < 16) ? &W2[(size_t)wr * DDIM]
                                  : &W3[(size_t)(wr - 16) * DDIM];

    #define S_LOAD(st, kt) do {                                             \
        int _k0 = (kt) * 64;                                                \
        cp16(smem_u32(&sx[st][xr][xc * 4]), xsrc + _k0 + xc * 4);           \
        cp16(smem_u32(&sw[st][wr][wc2 * 4]),       wsrc + _k0 + wc2 * 4);   \
        cp16(smem_u32(&sw[st][wr][(wc2 + 1) * 4]), wsrc + _k0 + (wc2 + 1) * 4); \
        CP_COMMIT();                                                        \
    } while (0)

    float acc[2] = {0.f, 0.f};

    S_LOAD(0, 0);
    S_LOAD(1, 1);

    for (int kt = 0; kt < 16; ++kt) {
        const int st = kt & 1;
        if (kt == 15) { CP_WAIT0(); } else { CP_WAIT1(); }
        __syncthreads();
        #pragma unroll
        for (int k4 = 0; k4 < 16; ++k4) {
            float4 xv = *reinterpret_cast<const float4*>(&sx[st][tok][k4 * 4]);
            #pragma unroll
            for (int j = 0; j < 2; ++j) {
                float4 wv = *reinterpret_cast<const float4*>(&sw[st][g * 2 + j][k4 * 4]);
                acc[j] += xv.x * wv.x + xv.y * wv.y + xv.z * wv.z + xv.w * wv.w;
            }
        }
        __syncthreads();
        if (kt + 2 < 16) S_LOAD(st, kt + 2);
    }

    #pragma unroll
    for (int j = 0; j < 2; ++j) sout[tok][g * 2 + j] = acc[j];
    __syncthreads();

    if (tid < 16) {
        float s = 0.f;
        #pragma unroll
        for (int n = 0; n < 16; ++n)
            s += (sout[tid][n] + b2[n]) * (sout[tid][16 + n] + b3[n]);
        g_s[t0 + tid] = s;
    }
}

// ---------------------------------------------------------------------------
// Kernel 1: mma.sync fp16 1-term GEMM, cp.async.bulk-fed, fused epilogue.
//   D = xhi @ whi^T  (error ~1e-4, measured headroom from R12)
//   y = x * softplus(D + b1) * s
// BM=BN=128, BK=64, 6-stage bulk pipeline (32KB/stage), 544 threads:
//   warps 0-15 compute (32x32 tiles, 4 warps/SMSP), warp 16 = producer.
// ---------------------------------------------------------------------------
#define NKT 16                    // 1024 / 64
#define STAGES 6
#define PART_B 16384              // one 128x64 fp16 tile
#define STAGE_B (2 * PART_B)      // A, B = 32KB
#define GEMM_SMEM (STAGES * STAGE_B)   // 196608

__global__ __launch_bounds__(544, 1) void gemm_kernel(
    const float* __restrict__ x,
    const float* __restrict__ b1,
    float* __restrict__ y)
{
    extern __shared__ __align__(1024) char smem[];
    __shared__ __align__(8) uint64_t mbar[2 * STAGES];  // full[0..5], empty[0..5]

    const uint32_t sdyn = smem_u32(smem);
    const uint32_t sFull  = smem_u32(&mbar[0]);
    const uint32_t sEmpty = smem_u32(&mbar[STAGES]);

    const int tid  = threadIdx.x;
    const int wid  = tid >> 5;
    const int lane = tid & 31;
    const int nb = blockIdx.x;          // 0..7
    const int mb = blockIdx.y;          // 0..31
    const int rbase = mb * 128;
    const int cbase = nb * 128;

    if (tid == 0) {
        #pragma unroll
        for (int s = 0; s < STAGES; ++s) {
            MBARRIER_INIT(sFull  + s * 8, 1);
            MBARRIER_INIT(sEmpty + s * 8, 16);
        }
    }
    __syncthreads();

    if (wid == 16) {
        // ---------------- producer ----------------
        if (lane == 0) {
            const char* xhiB = (const char*)g_xhi;
            const char* whiB = (const char*)g_whi;
            int st = 0, ph = 1;
            for (int kt = 0; kt < NKT; ++kt) {
                MBARRIER_WAIT_PARITY(sEmpty + st * 8, ph);
                uint32_t fb = sFull + st * 8;
                MBARRIER_EXPECT_TX(fb, STAGE_B);
                uint32_t sb = sdyn + st * STAGE_B;
                size_t ax = ((size_t)(mb * NKT + kt)) * PART_B;
                size_t bw = ((size_t)(nb * NKT + kt)) * PART_B;
                bulk_g2s(sb,          xhiB + ax, PART_B, fb);
                bulk_g2s(sb + PART_B, whiB + bw, PART_B, fb);
                if (++st == STAGES) { st = 0; ph ^= 1; }
            }
        }
        return;
    }

    // ---------------- consumers (warps 0-15), 32x32 warp tiles ----------------
    const int warp_m = wid & 3;    // row group: 32 rows
    const int warp_n = wid >> 2;   // col group: 32 cols

    float acc[2][4][4];
    #pragma unroll
    for (int i = 0; i < 2; ++i)
        #pragma unroll
        for (int j = 0; j < 4; ++j)
            #pragma unroll
            for (int e = 0; e < 4; ++e)
                acc[i][j][e] = 0.f;

    // A frag addresses: i in {0,1} (two m16 tiles)
    uint32_t aRow[2], aSw[2];
    #pragma unroll
    for (int i = 0; i < 2; ++i) {
        int r = warp_m * 32 + i * 16 + (lane & 15);
        aRow[i] = (uint32_t)r * 128;
        aSw[i]  = (uint32_t)(r & 7);
    }
    // B frag addresses via ldsm_x4: jj in {0,1}, each yields 2 n8 frags
    uint32_t bRow[2], bSw[2];
    #pragma unroll
    for (int jj = 0; jj < 2; ++jj) {
        int r = warp_n * 32 + jj * 16 + (lane & 7) + ((lane >> 4) & 1) * 8;
        bRow[jj] = (uint32_t)r * 128;
        bSw[jj]  = (uint32_t)(r & 7);
    }
    const uint32_t ac0 = (uint32_t)(lane >> 4);        // 0/1 (k8 half for A)
    const uint32_t bc0 = (uint32_t)((lane >> 3) & 1);  // 0/1 (k8 half for B)

    int st = 0, ph = 0;
    for (int kt = 0; kt < NKT; ++kt) {
        MBARRIER_WAIT_PARITY(sFull + st * 8, ph);
        const uint32_t sb = sdyn + st * STAGE_B;
        const uint32_t ah = sb;
        const uint32_t bh = sb + PART_B;

        #pragma unroll
        for (int kk = 0; kk < 4; ++kk) {       // four k16 steps of BK=64
            uint32_t Ah[2][4], Bf[2][4];
            const uint32_t ca = kk * 2 + ac0;
            const uint32_t cb = kk * 2 + bc0;
            #pragma unroll
            for (int i = 0; i < 2; ++i) {
                uint32_t off = aRow[i] + ((ca ^ aSw[i]) << 4);
                ldsm_x4(Ah[i], ah + off);
            }
            #pragma unroll
            for (int jj = 0; jj < 2; ++jj) {
                uint32_t off = bRow[jj] + ((cb ^ bSw[jj]) << 4);
                ldsm_x4(Bf[jj], bh + off);
            }
            #pragma unroll
            for (int i = 0; i < 2; ++i)
                #pragma unroll
                for (int j = 0; j < 4; ++j)
                    mma16816h(acc[i][j], Ah[i], &Bf[j >> 1][(j & 1) * 2]);
        }
        if (lane == 0) MBARRIER_ARRIVE(sEmpty + st * 8);
        if (++st == STAGES) { st = 0; ph ^= 1; }
    }

    // epilogue: y = x * softplus(acc + b1) * s
    #pragma unroll
    for (int i = 0; i < 2; ++i) {
        const int r0 = rbase + warp_m * 32 + i * 16 + (lane >> 2);
        const int r1 = r0 + 8;
        const float s0 = g_s[r0], s1 = g_s[r1];
        #pragma unroll
        for (int j = 0; j < 4; ++j) {
            const int c = cbase + warp_n * 32 + j * 8 + (lane & 3) * 2;
            float2 bv = *reinterpret_cast<const float2*>(b1 + c);
            float2 x0 = *reinterpret_cast<const float2*>(x + (size_t)r0 * DDIM + c);
            float2 x1 = *reinterpret_cast<const float2*>(x + (size_t)r1 * DDIM + c);
            float2 o0, o1;
            o0.x = x0.x * softplusf(acc[i][j][0] + bv.x) * s0;
            o0.y = x0.y * softplusf(acc[i][j][1] + bv.y) * s0;
            o1.x = x1.x * softplusf(acc[i][j][2] + bv.x) * s1;
            o1.y = x1.y * softplusf(acc[i][j][3] + bv.y) * s1;
            *reinterpret_cast<float2*>(y + (size_t)r0 * DDIM + c) = o0;
            *reinterpret_cast<float2*>(y + (size_t)r1 * DDIM + c) = o1;
        }
    }
}

// ---------------------------------------------------------------------------
extern "C" void kernel_launch(void* const* d_in, const int* in_sizes, int n_in,
                              void* d_out, int out_size)
{
    const float* x  = (const float*)d_in[0];
    const float* W1 = (const float*)d_in[1];
    const float* b1 = (const float*)d_in[2];
    const float* W2 = (const float*)d_in[3];
    const float* b2 = (const float*)d_in[4];
    const float* W3 = (const float*)d_in[5];
    const float* b3 = (const float*)d_in[6];
    // d_in[7] = A is mathematically dead (multiplies zero-initialized h).
    float* y = (float*)d_out;

    cudaFuncSetAttribute(gemm_kernel,
                         cudaFuncAttributeMaxDynamicSharedMemorySize, GEMM_SMEM);

    prep_kernel<<<896, 256>>>(x, W1, W2, b2, W3, b3);

    dim3 grid(DDIM / 128, TOKENS / 128);   // (8, 32)
    gemm_kernel<<<grid, 544, GEMM_SMEM>>>(x, b1, y);
}

// round 14
// speedup vs baseline: 2.7203x; 1.7342x over previous
#include <cuda_runtime.h>
#include <cuda_fp16.h>
#include <math.h>
#include <stdint.h>

#define TOKENS 4096
#define DDIM   1024

// ---------------------------------------------------------------------------
// scratch (__device__ globals; no cudaMalloc allowed)
// fp16 tiles, 128 rows x 64 cols = 16KB, SW128-pre-swizzled
// x: 32 mb x 16 kt = 512 tiles;  W1: 8 nb x 16 kt = 128 tiles
// w23: 16 kt tiles of 32 rows x 64 cols (rows 0-15 = W2, 16-31 = W3), 4KB each
// ---------------------------------------------------------------------------
__device__ float g_s[TOKENS];
__device__ int   g_s_flag[32];
__device__ __align__(1024) uint4 g_xhi[512 * 1024];
__device__ __align__(1024) uint4 g_whi[128 * 1024];
__device__ __align__(1024) uint4 g_w23[16 * 256];

__device__ __forceinline__ float softplusf(float z) {
    if (z > 20.0f) return z;
    return log1pf(expf(z));
}

__device__ __forceinline__ uint32_t smem_u32(const void* p) {
    uint32_t a;
    asm("{ .reg .u64 t; cvta.to.shared.u64 t, %1; cvt.u32.u64 %0, t; }"
        : "=r"(a) : "l"(p));
    return a;
}

#define MBARRIER_INIT(addr, cnt) \
    asm volatile("mbarrier.init.shared.b64 [%0], %1;" :: "r"(addr), "r"(cnt) : "memory")
#define MBARRIER_EXPECT_TX(addr, bytes) \
    asm volatile("mbarrier.arrive.expect_tx.shared.b64 _, [%0], %1;" \
        :: "r"(addr), "r"(bytes) : "memory")
#define MBARRIER_ARRIVE(addr) \
    asm volatile("mbarrier.arrive.shared.b64 _, [%0];" :: "r"(addr) : "memory")

#define MBARRIER_WAIT_PARITY(addr, parity) do { \
    uint32_t _m = (addr); uint32_t _p = (parity); uint32_t _d; \
    asm volatile("{\n\t.reg .pred p;\n\t" \
        "mbarrier.try_wait.parity.acquire.cta.shared::cta.b64 p, [%1], %2;\n\t" \
        "selp.b32 %0, 1, 0, p;\n\t}" : "=r"(_d) : "r"(_m), "r"(_p) : "memory"); \
    if (!_d) { \
        asm volatile("{\n\t.reg .pred P1;\n\t" \
            "WL_%=:\n\t" \
            "mbarrier.try_wait.parity.acquire.cta.shared::cta.b64 P1, [%0], %1, 0x989680;\n\t" \
            "@P1 bra.uni WD_%=;\n\t" \
            "bra.uni WL_%=;\n\t" \
            "WD_%=:\n\t}" :: "r"(_m), "r"(_p) : "memory"); \
    } \
} while (0)

__device__ __forceinline__ void bulk_g2s(uint32_t dst, const void* src,
                                         uint32_t bytes, uint32_t mbar) {
    asm volatile(
        "cp.async.bulk.shared::cluster.global.mbarrier::complete_tx::bytes "
        "[%0], [%1], %2, [%3];"
        :: "r"(dst), "l"(src), "r"(bytes), "r"(mbar) : "memory");
}

__device__ __forceinline__ void ldsm_x4(uint32_t* r, uint32_t addr) {
    asm volatile("ldmatrix.sync.aligned.m8n8.x4.shared.b16 {%0,%1,%2,%3}, [%4];"
                 : "=r"(r[0]), "=r"(r[1]), "=r"(r[2]), "=r"(r[3]) : "r"(addr));
}
__device__ __forceinline__ void mma16816h(float* d, const uint32_t* a,
                                          const uint32_t* b) {
    asm volatile(
        "mma.sync.aligned.m16n8k16.row.col.f32.f16.f16.f32 "
        "{%0,%1,%2,%3}, {%4,%5,%6,%7}, {%8,%9}, {%0,%1,%2,%3};"
        : "+f"(d[0]), "+f"(d[1]), "+f"(d[2]), "+f"(d[3])
        : "r"(a[0]), "r"(a[1]), "r"(a[2]), "r"(a[3]), "r"(b[0]), "r"(b[1]));
}

// ---------------------------------------------------------------------------
// Kernel 0 (prep = convert only):
//  blocks 0..511   : downcast x to fp16 128x64 tiles (SW128-pre-swizzled)
//  blocks 512..639 : downcast W1 likewise
//  blocks 640..655 : downcast W2/W3 into 32x64 w23 tiles (block = kt)
//  block  655 also zeroes g_s_flag
// ---------------------------------------------------------------------------
__global__ __launch_bounds__(256) void prep_kernel(
    const float* __restrict__ X, const float* __restrict__ W,
    const float* __restrict__ W2, const float* __restrict__ W3)
{
    const int bid = blockIdx.x;
    const int tid = threadIdx.x;

    if (bid >= 640) {
        // ---- w23 tiles ----
        const int kt = bid - 640;
        if (bid == 655 && tid >= 224) {   // zero flags (32 threads)
            g_s_flag[tid - 224] = 0;
        }
        int row = tid >> 3, c8 = tid & 7;
        const float* src = (row < 16) ? &W2[(size_t)row * DDIM]
                                      : &W3[(size_t)(row - 16) * DDIM];
        const float* p = src + kt * 64 + c8 * 8;
        float4 v0 = *reinterpret_cast<const float4*>(p);
        float4 v1 = *reinterpret_cast<const float4*>(p + 4);
        float v[8] = {v0.x, v0.y, v0.z, v0.w, v1.x, v1.y, v1.z, v1.w};
        uint32_t ph[4];
        #pragma unroll
        for (int i = 0; i < 4; ++i) {
            __half h0 = __float2half_rn(v[2 * i]);
            __half h1 = __float2half_rn(v[2 * i + 1]);
            ph[i] = (uint32_t)__half_as_ushort(h0) |
                    ((uint32_t)__half_as_ushort(h1) << 16);
        }
        uint32_t off = (uint32_t)(row * 128 + c8 * 16);
        off ^= ((off >> 3) & 0x70);
        g_w23[kt * 256 + (off >> 4)] = make_uint4(ph[0], ph[1], ph[2], ph[3]);
        return;
    }

    // ---- x / W1 tiles ----
    const float* src;
    uint4* dhi;
    if (bid < 512) {
        int mb = bid >> 4, kb = bid & 15;
        src = X + (size_t)mb * 128 * DDIM + kb * 64;
        dhi = g_xhi + (size_t)bid * 1024;
    } else {
        int t = bid - 512;
        int nb = t >> 4, kb = t & 15;
        src = W + (size_t)nb * 128 * DDIM + kb * 64;
        dhi = g_whi + (size_t)t * 1024;
    }
    #pragma unroll
    for (int it = 0; it < 4; ++it) {
        int c = tid + it * 256;
        int row = c >> 3, c8 = c & 7;
        const float* p = src + (size_t)row * DDIM + c8 * 8;
        float4 v0 = *reinterpret_cast<const float4*>(p);
        float4 v1 = *reinterpret_cast<const float4*>(p + 4);
        float v[8] = {v0.x, v0.y, v0.z, v0.w, v1.x, v1.y, v1.z, v1.w};
        uint32_t ph[4];
        #pragma unroll
        for (int i = 0; i < 4; ++i) {
            __half h0 = __float2half_rn(v[2 * i]);
            __half h1 = __float2half_rn(v[2 * i + 1]);
            ph[i] = (uint32_t)__half_as_ushort(h0) |
                    ((uint32_t)__half_as_ushort(h1) << 16);
        }
        uint32_t off = (uint32_t)(row * 128 + c8 * 16);
        off ^= ((off >> 3) & 0x70);   // SW128 swizzle, pre-applied
        dhi[off >> 4] = make_uint4(ph[0], ph[1], ph[2], ph[3]);
    }
}

// ---------------------------------------------------------------------------
// Kernel 1: fused GEMM + s computation.
// grid (9, 32): blockIdx.x == 0 -> s-CTA for row-block mb; else GEMM CTA.
// GEMM: D = xhi @ whi^T; y = x * softplus(D + b1) * s    (fp16 mma, fp32 acc)
// s-CTA: [Bm|Cm] = xhi @ w23^T (N=32); s = sum_n (Bm+b2)(Cm+b3); flag release.
// BM=BN=128, BK=64, 6-stage bulk pipeline, 544 threads.
// ---------------------------------------------------------------------------
#define NKT 16                    // 1024 / 64
#define STAGES 6
#define PART_B 16384              // one 128x64 fp16 tile
#define STAGE_B (2 * PART_B)      // 32KB
#define GEMM_SMEM (STAGES * STAGE_B)   // 196608
#define S_STAGE_TX (16384 + 4096)

__global__ __launch_bounds__(544, 1) void gemm_kernel(
    const float* __restrict__ x,
    const float* __restrict__ b1,
    const float* __restrict__ b2,
    const float* __restrict__ b3,
    float* __restrict__ y)
{
    extern __shared__ __align__(1024) char smem[];
    __shared__ __align__(8) uint64_t mbar[2 * STAGES];

    const uint32_t sdyn = smem_u32(smem);
    const uint32_t sFull  = smem_u32(&mbar[0]);
    const uint32_t sEmpty = smem_u32(&mbar[STAGES]);

    const int tid  = threadIdx.x;
    const int wid  = tid >> 5;
    const int lane = tid & 31;
    const int nbx = blockIdx.x;         // 0 = s-CTA, 1..8 = GEMM
    const int mb  = blockIdx.y;         // 0..31
    const int rbase = mb * 128;
    const bool is_s = (nbx == 0);

    if (tid == 0) {
        #pragma unroll
        for (int s = 0; s < STAGES; ++s) {
            MBARRIER_INIT(sFull  + s * 8, 1);
            MBARRIER_INIT(sEmpty + s * 8, is_s ? 8 : 16);
        }
    }
    __syncthreads();

    if (is_s) {
        // ==================== s-CTA ====================
        if (wid == 16) {
            if (lane == 0) {
                const char* xhiB = (const char*)g_xhi;
                const char* w23B = (const char*)g_w23;
                int st = 0, ph = 1;
                for (int kt = 0; kt < NKT; ++kt) {
                    MBARRIER_WAIT_PARITY(sEmpty + st * 8, ph);
                    uint32_t fb = sFull + st * 8;
                    MBARRIER_EXPECT_TX(fb, S_STAGE_TX);
                    uint32_t sb = sdyn + st * STAGE_B;
                    bulk_g2s(sb, xhiB + ((size_t)(mb * NKT + kt)) * PART_B,
                             PART_B, fb);
                    bulk_g2s(sb + PART_B, w23B + (size_t)kt * 4096, 4096, fb);
                    if (++st == STAGES) { st = 0; ph ^= 1; }
                }
            }
            return;
        }
        if (wid >= 8) return;   // warps 8-15 idle in s-CTA

        float acc[4][4];
        #pragma unroll
        for (int j = 0; j < 4; ++j)
            #pragma unroll
            for (int e = 0; e < 4; ++e)
                acc[j][e] = 0.f;

        const uint32_t aRow = (uint32_t)(wid * 16 + (lane & 15)) * 128;
        const uint32_t aSw  = (uint32_t)((wid * 16 + (lane & 15)) & 7);
        uint32_t bRow[2], bSw[2];
        #pragma unroll
        for (int jj = 0; jj < 2; ++jj) {
            int r = jj * 16 + (lane & 7) + ((lane >> 4) & 1) * 8;
            bRow[jj] = (uint32_t)r * 128;
            bSw[jj]  = (uint32_t)(r & 7);
        }
        const uint32_t ac0 = (uint32_t)(lane >> 4);
        const uint32_t bc0 = (uint32_t)((lane >> 3) & 1);

        int st = 0, ph = 0;
        for (int kt = 0; kt < NKT; ++kt) {
            MBARRIER_WAIT_PARITY(sFull + st * 8, ph);
            const uint32_t ah = sdyn + st * STAGE_B;
            const uint32_t bh = ah + PART_B;
            #pragma unroll
            for (int kk = 0; kk < 4; ++kk) {
                uint32_t Ah[4], Bf[2][4];
                const uint32_t ca = kk * 2 + ac0;
                const uint32_t cb = kk * 2 + bc0;
                ldsm_x4(Ah, ah + aRow + ((ca ^ aSw) << 4));
                #pragma unroll
                for (int jj = 0; jj < 2; ++jj)
                    ldsm_x4(Bf[jj], bh + bRow[jj] + ((cb ^ bSw[jj]) << 4));
                #pragma unroll
                for (int j = 0; j < 4; ++j)
                    mma16816h(acc[j], Ah, &Bf[j >> 1][(j & 1) * 2]);
            }
            if (lane == 0) MBARRIER_ARRIVE(sEmpty + st * 8);
            if (++st == STAGES) { st = 0; ph ^= 1; }
        }

        // s = sum_n (Bm + b2)(Cm + b3); cols 0-15 = Bm, 16-31 = Cm
        float s0 = 0.f, s1 = 0.f;
        #pragma unroll
        for (int j = 0; j < 2; ++j) {
            int n0 = j * 8 + (lane & 3) * 2;
            float b2a = b2[n0], b2b = b2[n0 + 1];
            float b3a = b3[n0], b3b = b3[n0 + 1];
            s0 += (acc[j][0] + b2a) * (acc[j + 2][0] + b3a)
                + (acc[j][1] + b2b) * (acc[j + 2][1] + b3b);
            s1 += (acc[j][2] + b2a) * (acc[j + 2][2] + b3a)
                + (acc[j][3] + b2b) * (acc[j + 2][3] + b3b);
        }
        s0 += __shfl_xor_sync(0xffffffffu, s0, 1);
        s0 += __shfl_xor_sync(0xffffffffu, s0, 2);
        s1 += __shfl_xor_sync(0xffffffffu, s1, 1);
        s1 += __shfl_xor_sync(0xffffffffu, s1, 2);
        if ((lane & 3) == 0) {
            int r = rbase + wid * 16 + (lane >> 2);
            g_s[r]     = s0;
            g_s[r + 8] = s1;
        }
        asm volatile("bar.sync 1, 256;" ::: "memory");
        if (tid == 0) {
            __threadfence();
            atomicExch(&g_s_flag[mb], 1);
        }
        return;
    }

    // ==================== GEMM CTA ====================
    const int cbase = (nbx - 1) * 128;

    if (wid == 16) {
        if (lane == 0) {
            const char* xhiB = (const char*)g_xhi;
            const char* whiB = (const char*)g_whi;
            int st = 0, ph = 1;
            for (int kt = 0; kt < NKT; ++kt) {
                MBARRIER_WAIT_PARITY(sEmpty + st * 8, ph);
                uint32_t fb = sFull + st * 8;
                MBARRIER_EXPECT_TX(fb, STAGE_B);
                uint32_t sb = sdyn + st * STAGE_B;
                size_t ax = ((size_t)(mb * NKT + kt)) * PART_B;
                size_t bw = ((size_t)((nbx - 1) * NKT + kt)) * PART_B;
                bulk_g2s(sb,          xhiB + ax, PART_B, fb);
                bulk_g2s(sb + PART_B, whiB + bw, PART_B, fb);
                if (++st == STAGES) { st = 0; ph ^= 1; }
            }
        }
        return;
    }

    const int warp_m = wid & 3;
    const int warp_n = wid >> 2;

    float acc[2][4][4];
    #pragma unroll
    for (int i = 0; i < 2; ++i)
        #pragma unroll
        for (int j = 0; j < 4; ++j)
            #pragma unroll
            for (int e = 0; e < 4; ++e)
                acc[i][j][e] = 0.f;

    uint32_t aRow[2], aSw[2];
    #pragma unroll
    for (int i = 0; i < 2; ++i) {
        int r = warp_m * 32 + i * 16 + (lane & 15);
        aRow[i] = (uint32_t)r * 128;
        aSw[i]  = (uint32_t)(r & 7);
    }
    uint32_t bRow[2], bSw[2];
    #pragma unroll
    for (int jj = 0; jj < 2; ++jj) {
        int r = warp_n * 32 + jj * 16 + (lane & 7) + ((lane >> 4) & 1) * 8;
        bRow[jj] = (uint32_t)r * 128;
        bSw[jj]  = (uint32_t)(r & 7);
    }
    const uint32_t ac0 = (uint32_t)(lane >> 4);
    const uint32_t bc0 = (uint32_t)((lane >> 3) & 1);

    int st = 0, ph = 0;
    for (int kt = 0; kt < NKT; ++kt) {
        MBARRIER_WAIT_PARITY(sFull + st * 8, ph);
        const uint32_t ah = sdyn + st * STAGE_B;
        const uint32_t bh = ah + PART_B;

        #pragma unroll
        for (int kk = 0; kk < 4; ++kk) {
            uint32_t Ah[2][4], Bf[2][4];
            const uint32_t ca = kk * 2 + ac0;
            const uint32_t cb = kk * 2 + bc0;
            #pragma unroll
            for (int i = 0; i < 2; ++i)
                ldsm_x4(Ah[i], ah + aRow[i] + ((ca ^ aSw[i]) << 4));
            #pragma unroll
            for (int jj = 0; jj < 2; ++jj)
                ldsm_x4(Bf[jj], bh + bRow[jj] + ((cb ^ bSw[jj]) << 4));
            #pragma unroll
            for (int i = 0; i < 2; ++i)
                #pragma unroll
                for (int j = 0; j < 4; ++j)
                    mma16816h(acc[i][j], Ah[i], &Bf[j >> 1][(j & 1) * 2]);
        }
        if (lane == 0) MBARRIER_ARRIVE(sEmpty + st * 8);
        if (++st == STAGES) { st = 0; ph ^= 1; }
    }

    // wait for s (long since done in the common case)
    {
        volatile int* f = (volatile int*)&g_s_flag[mb];
        while (*f == 0) {}
        __threadfence();
    }

    // epilogue: y = x * softplus(acc + b1) * s
    #pragma unroll
    for (int i = 0; i < 2; ++i) {
        const int r0 = rbase + warp_m * 32 + i * 16 + (lane >> 2);
        const int r1 = r0 + 8;
        const float s0 = g_s[r0], s1 = g_s[r1];
        #pragma unroll
        for (int j = 0; j < 4; ++j) {
            const int c = cbase + warp_n * 32 + j * 8 + (lane & 3) * 2;
            float2 bv = *reinterpret_cast<const float2*>(b1 + c);
            float2 x0 = *reinterpret_cast<const float2*>(x + (size_t)r0 * DDIM + c);
            float2 x1 = *reinterpret_cast<const float2*>(x + (size_t)r1 * DDIM + c);
            float2 o0, o1;
            o0.x = x0.x * softplusf(acc[i][j][0] + bv.x) * s0;
            o0.y = x0.y * softplusf(acc[i][j][1] + bv.y) * s0;
            o1.x = x1.x * softplusf(acc[i][j][2] + bv.x) * s1;
            o1.y = x1.y * softplusf(acc[i][j][3] + bv.y) * s1;
            *reinterpret_cast<float2*>(y + (size_t)r0 * DDIM + c) = o0;
            *reinterpret_cast<float2*>(y + (size_t)r1 * DDIM + c) = o1;
        }
    }
}

// ---------------------------------------------------------------------------
extern "C" void kernel_launch(void* const* d_in, const int* in_sizes, int n_in,
                              void* d_out, int out_size)
{
    const float* x  = (const float*)d_in[0];
    const float* W1 = (const float*)d_in[1];
    const float* b1 = (const float*)d_in[2];
    const float* W2 = (const float*)d_in[3];
    const float* b2 = (const float*)d_in[4];
    const float* W3 = (const float*)d_in[5];
    const float* b3 = (const float*)d_in[6];
    // d_in[7] = A is mathematically dead (multiplies zero-initialized h).
    float* y = (float*)d_out;

    cudaFuncSetAttribute(gemm_kernel,
                         cudaFuncAttributeMaxDynamicSharedMemorySize, GEMM_SMEM);

    prep_kernel<<<656, 256>>>(x, W1, W2, W3);

    dim3 grid(9, TOKENS / 128);   // x=0: s-CTAs; x=1..8: GEMM
    gemm_kernel<<<grid, 544, GEMM_SMEM>>>(x, b1, b2, b3, y);
}